// round 1
// baseline (speedup 1.0000x reference)
#include <cuda_runtime.h>
#include <cstdint>

// ---------------------------------------------------------------------------
// InnerMonologue: parity mask + two GEMMs + masked blend.
// Shapes (from reference): B=4, S=8192, H=2048, P=256 (derived at runtime).
// Output layout (float32, concatenated in reference return order):
//   [0, BS*P)              private_reasoning
//   [BS*P, BS*P+BS*H)      output
//   [.., +BS)              is_private (0.0/1.0)
//   [.., +B)               subspace_usage
// ---------------------------------------------------------------------------

#define MAX_S 32768
__device__ unsigned char g_mask[MAX_S];

// ---------------------------------------------------------------------------
// Kernel 0: parity scan over token_ids[0,:], writes g_mask, is_private, usage.
// Single block, 256 threads.
// ---------------------------------------------------------------------------
__global__ void mask_kernel(const int* __restrict__ tok,
                            const int* __restrict__ ttid_p,
                            float* __restrict__ is_priv_out,  // BS floats
                            float* __restrict__ usage_out,    // B floats
                            int B, int S) {
    const int ttid = *ttid_p;
    const int tid = threadIdx.x;
    const int nthreads = 256;
    const int chunk = (S + nthreads - 1) / nthreads;
    const int start = tid * chunk;
    const int end = min(start + chunk, S);

    __shared__ int sc[256];

    // Per-chunk match counts
    int cnt = 0;
    for (int i = start; i < end; i++) cnt += (tok[i] == ttid);
    sc[tid] = cnt;
    __syncthreads();

    // Inclusive Hillis-Steele scan
    for (int off = 1; off < nthreads; off <<= 1) {
        int v = 0;
        if (tid >= off) v = sc[tid - off];
        __syncthreads();
        sc[tid] += v;
        __syncthreads();
    }
    const int excl = sc[tid] - cnt;

    // Write parity mask for this chunk, count ones.
    int run = excl;
    int ones = 0;
    for (int i = start; i < end; i++) {
        run += (tok[i] == ttid);
        unsigned char m = (unsigned char)(run & 1);
        g_mask[i] = m;
        ones += m;
    }
    __syncthreads();
    sc[tid] = ones;
    __syncthreads();
    for (int off = 128; off > 0; off >>= 1) {
        if (tid < off) sc[tid] += sc[tid + off];
        __syncthreads();
    }
    const float usage = (float)sc[0] / (float)S;
    if (tid < B) usage_out[tid] = usage;
    __syncthreads();

    // is_private broadcast over batch
    const int BS = B * S;
    for (int idx = tid; idx < BS; idx += nthreads)
        is_priv_out[idx] = (float)g_mask[idx % S];
}

// ---------------------------------------------------------------------------
// Kernel 1: C[M,N] = A[M,K] @ W[K,N] + bias[N]   (128x128 tile, BK=8)
// 256 threads, each computes an 8x8 micro-tile. All dims divisible by tile.
// ---------------------------------------------------------------------------
__global__ __launch_bounds__(256, 2)
void gemm_bias_kernel(const float* __restrict__ A,
                      const float* __restrict__ W,
                      const float* __restrict__ bias,
                      float* __restrict__ C,
                      int M, int N, int K) {
    __shared__ float As[8][128];
    __shared__ float Bs[8][128];

    const int bx = blockIdx.x;  // column block
    const int by = blockIdx.y;  // row block
    const int tid = threadIdx.x;
    const int tx = tid & 15;
    const int ty = tid >> 4;

    const float* Ab = A + (size_t)by * 128 * K;
    const float* Wb = W + (size_t)bx * 128;

    const int arow = tid >> 1;
    const int acol4 = (tid & 1) * 4;
    const int brow = tid >> 5;
    const int bcol4 = (tid & 31) * 4;

    float acc[8][8];
#pragma unroll
    for (int i = 0; i < 8; i++)
#pragma unroll
        for (int j = 0; j < 8; j++) acc[i][j] = 0.f;

    for (int k0 = 0; k0 < K; k0 += 8) {
        float4 av = *(const float4*)&Ab[(size_t)arow * K + k0 + acol4];
        As[acol4 + 0][arow] = av.x;
        As[acol4 + 1][arow] = av.y;
        As[acol4 + 2][arow] = av.z;
        As[acol4 + 3][arow] = av.w;
        *(float4*)&Bs[brow][bcol4] =
            *(const float4*)&Wb[(size_t)(k0 + brow) * N + bcol4];
        __syncthreads();

#pragma unroll
        for (int k = 0; k < 8; k++) {
            float a[8], b[8];
            *(float4*)&a[0] = *(const float4*)&As[k][ty * 8];
            *(float4*)&a[4] = *(const float4*)&As[k][ty * 8 + 4];
            *(float4*)&b[0] = *(const float4*)&Bs[k][tx * 8];
            *(float4*)&b[4] = *(const float4*)&Bs[k][tx * 8 + 4];
#pragma unroll
            for (int i = 0; i < 8; i++)
#pragma unroll
                for (int j = 0; j < 8; j++) acc[i][j] += a[i] * b[j];
        }
        __syncthreads();
    }

    // Epilogue: add bias, store.
#pragma unroll
    for (int i = 0; i < 8; i++) {
        const int row = by * 128 + ty * 8 + i;
#pragma unroll
        for (int j = 0; j < 8; j += 4) {
            const int col = bx * 128 + tx * 8 + j;
            float4 v;
            v.x = acc[i][j + 0] + bias[col + 0];
            v.y = acc[i][j + 1] + bias[col + 1];
            v.z = acc[i][j + 2] + bias[col + 2];
            v.w = acc[i][j + 3] + bias[col + 3];
            *(float4*)&C[(size_t)row * N + col] = v;
        }
    }
}

// ---------------------------------------------------------------------------
// Kernel 2: OUT = mask ? (PR @ W_from + b_from) : HS
// Same tile shape; whole-block skip when no row in the 128-row tile is private.
// ---------------------------------------------------------------------------
__global__ __launch_bounds__(256, 2)
void gemm2_blend_kernel(const float* __restrict__ PR,   // [M,K]
                        const float* __restrict__ W,    // [K,N]
                        const float* __restrict__ bias, // [N]
                        const float* __restrict__ HS,   // [M,N]
                        float* __restrict__ OUT,        // [M,N]
                        int M, int N, int K, int S) {
    __shared__ float As[8][128];
    __shared__ float Bs[8][128];
    __shared__ unsigned char smask[128];
    __shared__ int s_cnt;

    const int bx = blockIdx.x;
    const int by = blockIdx.y;
    const int tid = threadIdx.x;

    if (tid == 0) s_cnt = 0;
    __syncthreads();
    if (tid < 128) {
        unsigned char m = g_mask[(by * 128 + tid) % S];
        smask[tid] = m;
        if (m) atomicAdd(&s_cnt, 1);
    }
    __syncthreads();

    if (s_cnt == 0) {
        // All-public tile: straight copy of HS slab.
        const size_t base = (size_t)(by * 128) * N + bx * 128;
        const float* src = HS + base;
        float* dst = OUT + base;
        for (int i = tid; i < 128 * 32; i += 256) {
            const int r = i >> 5;
            const int c = (i & 31) * 4;
            *(float4*)&dst[(size_t)r * N + c] =
                *(const float4*)&src[(size_t)r * N + c];
        }
        return;
    }

    const int tx = tid & 15;
    const int ty = tid >> 4;

    const float* Ab = PR + (size_t)by * 128 * K;
    const float* Wb = W + (size_t)bx * 128;

    const int arow = tid >> 1;
    const int acol4 = (tid & 1) * 4;
    const int brow = tid >> 5;
    const int bcol4 = (tid & 31) * 4;

    float acc[8][8];
#pragma unroll
    for (int i = 0; i < 8; i++)
#pragma unroll
        for (int j = 0; j < 8; j++) acc[i][j] = 0.f;

    for (int k0 = 0; k0 < K; k0 += 8) {
        float4 av = *(const float4*)&Ab[(size_t)arow * K + k0 + acol4];
        As[acol4 + 0][arow] = av.x;
        As[acol4 + 1][arow] = av.y;
        As[acol4 + 2][arow] = av.z;
        As[acol4 + 3][arow] = av.w;
        *(float4*)&Bs[brow][bcol4] =
            *(const float4*)&Wb[(size_t)(k0 + brow) * N + bcol4];
        __syncthreads();

#pragma unroll
        for (int k = 0; k < 8; k++) {
            float a[8], b[8];
            *(float4*)&a[0] = *(const float4*)&As[k][ty * 8];
            *(float4*)&a[4] = *(const float4*)&As[k][ty * 8 + 4];
            *(float4*)&b[0] = *(const float4*)&Bs[k][tx * 8];
            *(float4*)&b[4] = *(const float4*)&Bs[k][tx * 8 + 4];
#pragma unroll
            for (int i = 0; i < 8; i++)
#pragma unroll
                for (int j = 0; j < 8; j++) acc[i][j] += a[i] * b[j];
        }
        __syncthreads();
    }

#pragma unroll
    for (int i = 0; i < 8; i++) {
        const int lrow = ty * 8 + i;
        const int row = by * 128 + lrow;
        const unsigned char m = smask[lrow];
#pragma unroll
        for (int j = 0; j < 8; j += 4) {
            const int col = bx * 128 + tx * 8 + j;
            float4 v;
            if (m) {
                v.x = acc[i][j + 0] + bias[col + 0];
                v.y = acc[i][j + 1] + bias[col + 1];
                v.z = acc[i][j + 2] + bias[col + 2];
                v.w = acc[i][j + 3] + bias[col + 3];
            } else {
                v = *(const float4*)&HS[(size_t)row * N + col];
            }
            *(float4*)&OUT[(size_t)row * N + col] = v;
        }
    }
}

// ---------------------------------------------------------------------------
extern "C" void kernel_launch(void* const* d_in, const int* in_sizes, int n_in,
                              void* d_out, int out_size) {
    const float* hidden = (const float*)d_in[0];  // B*S*H
    const float* W_to   = (const float*)d_in[1];  // H*P
    const float* b_to   = (const float*)d_in[2];  // P
    const float* W_from = (const float*)d_in[3];  // P*H
    const float* b_from = (const float*)d_in[4];  // H
    const int*   token  = (const int*)d_in[5];    // B*S
    const int*   ttid   = (const int*)d_in[6];    // 1

    const int P  = in_sizes[2];
    const int H  = in_sizes[4];
    const int BS = in_sizes[5];
    const int B  = out_size - BS * (P + H + 1);
    const int S  = BS / B;

    float* out = (float*)d_out;
    float* out_pr    = out;                         // BS*P
    float* out_o     = out + (size_t)BS * P;        // BS*H
    float* out_mask  = out_o + (size_t)BS * H;      // BS
    float* out_usage = out_mask + BS;               // B

    // K0: mask, is_private, usage
    mask_kernel<<<1, 256>>>(token, ttid, out_mask, out_usage, B, S);

    // K1: PR = HS @ W_to + b_to    (M=BS, N=P, K=H)
    {
        dim3 grid(P / 128, BS / 128);
        gemm_bias_kernel<<<grid, 256>>>(hidden, W_to, b_to, out_pr, BS, P, H);
    }

    // K2: OUT = blend(PR @ W_from + b_from, HS)   (M=BS, N=H, K=P)
    {
        dim3 grid(H / 128, BS / 128);
        gemm2_blend_kernel<<<grid, 256>>>(out_pr, W_from, b_from, hidden,
                                          out_o, BS, H, P, S);
    }
}

// round 5
// speedup vs baseline: 1.7636x; 1.7636x over previous
#include <cuda_runtime.h>
#include <cuda_bf16.h>
#include <cstdint>

// ===========================================================================
// InnerMonologue via mma.sync bf16-split (tcgen05 unavailable on this target).
// Static SMEM (<48KB); weight globals referenced ONLY from device code
// (template-selected), never passed as host-side kernel args.
// Output: [PR (BS*P)] [OUT (BS*H)] [is_private (BS)] [usage (B)]  (all fp32)
// ===========================================================================

#define MAX_S 32768
#define MAX_WE (2048 * 256)

__device__ unsigned char g_mask[MAX_S];
__device__ __nv_bfloat16 g_Wt_hi[MAX_WE];  // W_to  transposed [P][H]
__device__ __nv_bfloat16 g_Wt_lo[MAX_WE];
__device__ __nv_bfloat16 g_Wf_hi[MAX_WE];  // W_from transposed [H][P]
__device__ __nv_bfloat16 g_Wf_lo[MAX_WE];

__device__ __forceinline__ uint32_t smem_u32(const void* p) {
    uint32_t a;
    asm("{ .reg .u64 t; cvta.to.shared.u64 t, %1; cvt.u32.u64 %0, t; }"
        : "=r"(a) : "l"(p));
    return a;
}
__device__ __forceinline__ void ldsm_x4(uint32_t addr, uint32_t* r) {
    asm volatile("ldmatrix.sync.aligned.m8n8.x4.shared.b16 {%0,%1,%2,%3}, [%4];"
                 : "=r"(r[0]), "=r"(r[1]), "=r"(r[2]), "=r"(r[3])
                 : "r"(addr));
}
__device__ __forceinline__ void mma_bf16(float* c, const uint32_t* a,
                                         const uint32_t* b) {
    asm volatile(
        "mma.sync.aligned.m16n8k16.row.col.f32.bf16.bf16.f32 "
        "{%0,%1,%2,%3}, {%4,%5,%6,%7}, {%8,%9}, {%0,%1,%2,%3};"
        : "+f"(c[0]), "+f"(c[1]), "+f"(c[2]), "+f"(c[3])
        : "r"(a[0]), "r"(a[1]), "r"(a[2]), "r"(a[3]), "r"(b[0]), "r"(b[1]));
}
__device__ __forceinline__ void split2(float x, float y, uint32_t& hi,
                                       uint32_t& lo) {
    __nv_bfloat16 hx = __float2bfloat16_rn(x);
    __nv_bfloat16 hy = __float2bfloat16_rn(y);
    hi = (uint32_t)__bfloat16_as_ushort(hx) |
         ((uint32_t)__bfloat16_as_ushort(hy) << 16);
    __nv_bfloat16 lx = __float2bfloat16_rn(x - __bfloat162float(hx));
    __nv_bfloat16 ly = __float2bfloat16_rn(y - __bfloat162float(hy));
    lo = (uint32_t)__bfloat16_as_ushort(lx) |
         ((uint32_t)__bfloat16_as_ushort(ly) << 16);
}

// Tile rows: 40 bf16 (80 bytes) -> conflict-free ldmatrix (stride 20 banks).
#define ROWB 80
#define TILE_BYTES (128 * ROWB)  // 10240; 4 tiles = 40960B static smem

// ===========================================================================
// GEMM: C[128,128] tile = A[M,K](fp32) @ B[N,K](bf16 hi/lo)^T + bias, blend.
// 256 threads = 8 warps, each a 32(M) x 64(N) warp tile. BK=32, single stage
// with register prefetch of the next chunk.  USE_WF selects weight globals.
// ===========================================================================
template <bool MASKED, bool USE_WF>
__global__ void __launch_bounds__(256, 1)
gemm_mma(const float* __restrict__ A, const float* __restrict__ bias,
         const float* __restrict__ HS, float* __restrict__ OUT,
         int K, int Ntot, int S) {
    __shared__ __align__(16) char sAh[TILE_BYTES];
    __shared__ __align__(16) char sAl[TILE_BYTES];
    __shared__ __align__(16) char sBh[TILE_BYTES];
    __shared__ __align__(16) char sBl[TILE_BYTES];
    __shared__ unsigned char smask[128];
    __shared__ int s_cnt;

    const __nv_bfloat16* __restrict__ Bh = USE_WF ? g_Wf_hi : g_Wt_hi;
    const __nv_bfloat16* __restrict__ Bl = USE_WF ? g_Wf_lo : g_Wt_lo;

    const int tid = threadIdx.x;
    const int wid = tid >> 5;
    const int lane = tid & 31;
    const int m0 = blockIdx.y * 128;
    const int n0 = blockIdx.x * 128;

    if (MASKED) {
        if (tid == 0) s_cnt = 0;
        __syncthreads();
        if (tid < 128) {
            unsigned char mm = g_mask[(m0 + tid) % S];
            smask[tid] = mm;
            if (mm) atomicAdd(&s_cnt, 1);
        }
        __syncthreads();
        if (s_cnt == 0) {  // all-public tile: straight copy of HS slab
            const size_t base = (size_t)m0 * Ntot + n0;
            for (int i = tid; i < 128 * 32; i += 256) {
                int r = i >> 5, c = (i & 31) << 2;
                *(float4*)&OUT[base + (size_t)r * Ntot + c] =
                    *(const float4*)&HS[base + (size_t)r * Ntot + c];
            }
            return;
        }
    }

    const uint32_t uAh = smem_u32(sAh);
    const uint32_t uAl = smem_u32(sAl);
    const uint32_t uBh = smem_u32(sBh);
    const uint32_t uBl = smem_u32(sBl);

    const int wm = (wid >> 1) * 32;  // warp M offset (4 warps)
    const int wn = (wid & 1) * 64;   // warp N offset (2 warps)

    const int lrow = tid >> 1;        // 0..127
    const int lcol = (tid & 1) * 16;  // 0 or 16

    float acc[2][8][4];
#pragma unroll
    for (int mt = 0; mt < 2; mt++)
#pragma unroll
        for (int nt = 0; nt < 8; nt++)
#pragma unroll
            for (int i = 0; i < 4; i++) acc[mt][nt][i] = 0.f;

    const int nk = K >> 5;
    float areg[16];
    uint4 bregh[2], bregl[2];

    auto load_regs = [&](int s) {
        const int k0 = s << 5;
        const float* ap = A + (size_t)(m0 + lrow) * K + k0 + lcol;
#pragma unroll
        for (int i = 0; i < 4; i++)
            *(float4*)&areg[i * 4] = *(const float4*)(ap + i * 4);
        const size_t bo = (size_t)(n0 + lrow) * K + k0 + lcol;
        bregh[0] = *(const uint4*)(Bh + bo);
        bregh[1] = *(const uint4*)(Bh + bo + 8);
        bregl[0] = *(const uint4*)(Bl + bo);
        bregl[1] = *(const uint4*)(Bl + bo + 8);
    };
    auto store_stage = [&]() {
        uint32_t h[8], l[8];
#pragma unroll
        for (int i = 0; i < 8; i++)
            split2(areg[2 * i], areg[2 * i + 1], h[i], l[i]);
        const int off = lrow * ROWB + lcol * 2;
        *(uint4*)(sAh + off) = make_uint4(h[0], h[1], h[2], h[3]);
        *(uint4*)(sAh + off + 16) = make_uint4(h[4], h[5], h[6], h[7]);
        *(uint4*)(sAl + off) = make_uint4(l[0], l[1], l[2], l[3]);
        *(uint4*)(sAl + off + 16) = make_uint4(l[4], l[5], l[6], l[7]);
        *(uint4*)(sBh + off) = bregh[0];
        *(uint4*)(sBh + off + 16) = bregh[1];
        *(uint4*)(sBl + off) = bregl[0];
        *(uint4*)(sBl + off + 16) = bregl[1];
    };
    auto compute = [&]() {
        const int r8 = lane & 7;
        const int mat = lane >> 3;  // 0..3
#pragma unroll
        for (int ks = 0; ks < 2; ks++) {
            uint32_t ahf[2][4], alf[2][4];
#pragma unroll
            for (int mt = 0; mt < 2; mt++) {
                int arow = wm + mt * 16 + (mat & 1) * 8 + r8;
                int acol = ks * 16 + (mat >> 1) * 8;
                uint32_t off = (uint32_t)(arow * ROWB + acol * 2);
                ldsm_x4(uAh + off, ahf[mt]);
                ldsm_x4(uAl + off, alf[mt]);
            }
            uint32_t bhf[8][2], blf[8][2];
#pragma unroll
            for (int g = 0; g < 4; g++) {
                int brow = wn + g * 16 + (mat & 1) * 8 + r8;
                int bcol = ks * 16 + (mat >> 1) * 8;
                uint32_t off = (uint32_t)(brow * ROWB + bcol * 2);
                uint32_t t[4];
                ldsm_x4(uBh + off, t);
                bhf[2 * g][0] = t[0]; bhf[2 * g][1] = t[2];
                bhf[2 * g + 1][0] = t[1]; bhf[2 * g + 1][1] = t[3];
                ldsm_x4(uBl + off, t);
                blf[2 * g][0] = t[0]; blf[2 * g][1] = t[2];
                blf[2 * g + 1][0] = t[1]; blf[2 * g + 1][1] = t[3];
            }
#pragma unroll
            for (int mt = 0; mt < 2; mt++)
#pragma unroll
                for (int nt = 0; nt < 8; nt++) {
                    mma_bf16(acc[mt][nt], ahf[mt], bhf[nt]);
                    mma_bf16(acc[mt][nt], ahf[mt], blf[nt]);
                    mma_bf16(acc[mt][nt], alf[mt], bhf[nt]);
                }
        }
    };

    // Main loop: single smem stage, register prefetch of next chunk.
    load_regs(0);
    for (int s = 0; s < nk; s++) {
        store_stage();
        __syncthreads();
        if (s + 1 < nk) load_regs(s + 1);  // globals in flight during compute
        compute();
        __syncthreads();
    }

    // Epilogue
    const int qr = lane >> 2;
    const int qc = (lane & 3) * 2;
#pragma unroll
    for (int mt = 0; mt < 2; mt++) {
        const int lr0 = wm + mt * 16 + qr;
        const int lr1 = lr0 + 8;
        const size_t rb0 = (size_t)(m0 + lr0) * Ntot;
        const size_t rb1 = (size_t)(m0 + lr1) * Ntot;
        const bool p0 = !MASKED || (smask[lr0] != 0);
        const bool p1 = !MASKED || (smask[lr1] != 0);
#pragma unroll
        for (int nt = 0; nt < 8; nt++) {
            const int col = n0 + wn + nt * 8 + qc;
            float2 b2 = *(const float2*)&bias[col];
            float2 v0, v1;
            if (p0) {
                v0.x = acc[mt][nt][0] + b2.x;
                v0.y = acc[mt][nt][1] + b2.y;
            } else {
                v0 = *(const float2*)&HS[rb0 + col];
            }
            if (p1) {
                v1.x = acc[mt][nt][2] + b2.x;
                v1.y = acc[mt][nt][3] + b2.y;
            } else {
                v1 = *(const float2*)&HS[rb1 + col];
            }
            *(float2*)&OUT[rb0 + col] = v0;
            *(float2*)&OUT[rb1 + col] = v1;
        }
    }
}

// ===========================================================================
// Mask scan, broadcast, weight split kernels.
// ===========================================================================
__global__ void scan_kernel(const int* __restrict__ tok,
                            const int* __restrict__ ttid_p,
                            float* __restrict__ usage_out, int B, int S) {
    __shared__ int stok[8192];
    __shared__ int sc[256];
    const int ttid = *ttid_p;
    const int tid = threadIdx.x;
    const bool fits = (S <= 8192);
    if (fits)
        for (int i = tid; i < S; i += 256) stok[i] = tok[i];
    __syncthreads();
    const int* src = fits ? stok : tok;

    const int chunk = (S + 255) / 256;
    const int start = tid * chunk;
    const int end = min(start + chunk, S);
    int cnt = 0;
    for (int i = start; i < end; i++) cnt += (src[i] == ttid);
    sc[tid] = cnt;
    __syncthreads();
    for (int off = 1; off < 256; off <<= 1) {
        int v = (tid >= off) ? sc[tid - off] : 0;
        __syncthreads();
        sc[tid] += v;
        __syncthreads();
    }
    int run = sc[tid] - cnt;
    int ones = 0;
    for (int i = start; i < end; i++) {
        run += (src[i] == ttid);
        unsigned char m = (unsigned char)(run & 1);
        g_mask[i] = m;
        ones += m;
    }
    __syncthreads();
    sc[tid] = ones;
    __syncthreads();
    for (int off = 128; off > 0; off >>= 1) {
        if (tid < off) sc[tid] += sc[tid + off];
        __syncthreads();
    }
    if (tid < B) usage_out[tid] = (float)sc[0] / (float)S;
}

__global__ void bcast_kernel(float* __restrict__ out_mask, int BS, int S) {
    int i = blockIdx.x * blockDim.x + threadIdx.x;
    if (i < BS) out_mask[i] = (float)g_mask[i % S];
}

__global__ void conv_w_kernel(const float* __restrict__ W_to,
                              const float* __restrict__ W_from, int H, int P) {
    int idx = blockIdx.x * blockDim.x + threadIdx.x;
    if (idx >= H * P) return;
    {  // W_to [H][P] -> Wt [P][H]
        float v = W_to[idx];
        int k = idx / P, n = idx - k * P;
        __nv_bfloat16 h = __float2bfloat16_rn(v);
        g_Wt_hi[n * H + k] = h;
        g_Wt_lo[n * H + k] = __float2bfloat16_rn(v - __bfloat162float(h));
    }
    {  // W_from [P][H] -> Wf [H][P]
        float v = W_from[idx];
        int p = idx / H, hh = idx - p * H;
        __nv_bfloat16 h = __float2bfloat16_rn(v);
        g_Wf_hi[hh * P + p] = h;
        g_Wf_lo[hh * P + p] = __float2bfloat16_rn(v - __bfloat162float(h));
    }
}

// ===========================================================================
extern "C" void kernel_launch(void* const* d_in, const int* in_sizes, int n_in,
                              void* d_out, int out_size) {
    const float* hidden = (const float*)d_in[0];
    const float* W_to   = (const float*)d_in[1];
    const float* b_to   = (const float*)d_in[2];
    const float* W_from = (const float*)d_in[3];
    const float* b_from = (const float*)d_in[4];
    const int*   token  = (const int*)d_in[5];
    const int*   ttid   = (const int*)d_in[6];

    const int P  = in_sizes[2];
    const int H  = in_sizes[4];
    const int BS = in_sizes[5];
    const int B  = out_size - BS * (P + H + 1);
    const int S  = BS / B;

    float* out = (float*)d_out;
    float* out_pr    = out;
    float* out_o     = out + (size_t)BS * P;
    float* out_mask  = out_o + (size_t)BS * H;
    float* out_usage = out_mask + BS;

    scan_kernel<<<1, 256>>>(token, ttid, out_usage, B, S);
    bcast_kernel<<<(BS + 255) / 256, 256>>>(out_mask, BS, S);
    conv_w_kernel<<<(H * P + 255) / 256, 256>>>(W_to, W_from, H, P);

    // GEMM1: PR = HS @ W_to + b_to   (M=BS, N=P, K=H)
    gemm_mma<false, false><<<dim3(P / 128, BS / 128), 256>>>(
        hidden, b_to, nullptr, out_pr, H, P, S);

    // GEMM2: OUT = blend(PR @ W_from + b_from, HS)  (M=BS, N=H, K=P)
    gemm_mma<true, true><<<dim3(H / 128, BS / 128), 256>>>(
        out_pr, b_from, hidden, out_o, P, H, S);
}

// round 6
// speedup vs baseline: 1.9204x; 1.0889x over previous
#include <cuda_runtime.h>
#include <cuda_bf16.h>
#include <cstdint>

// ===========================================================================
// InnerMonologue via mma.sync bf16-split. 512-thread GEMM CTAs (16 warps) for
// latency hiding; static SMEM <48KB; weight globals selected by template.
// Output: [PR (BS*P)] [OUT (BS*H)] [is_private (BS)] [usage (B)]  (all fp32)
// ===========================================================================

#define MAX_S 32768
#define MAX_WE (2048 * 256)

__device__ unsigned char g_mask[MAX_S];
__device__ __nv_bfloat16 g_Wt_hi[MAX_WE];  // W_to  transposed [P][H]
__device__ __nv_bfloat16 g_Wt_lo[MAX_WE];
__device__ __nv_bfloat16 g_Wf_hi[MAX_WE];  // W_from transposed [H][P]
__device__ __nv_bfloat16 g_Wf_lo[MAX_WE];

__device__ __forceinline__ uint32_t smem_u32(const void* p) {
    uint32_t a;
    asm("{ .reg .u64 t; cvta.to.shared.u64 t, %1; cvt.u32.u64 %0, t; }"
        : "=r"(a) : "l"(p));
    return a;
}
__device__ __forceinline__ void ldsm_x4(uint32_t addr, uint32_t* r) {
    asm volatile("ldmatrix.sync.aligned.m8n8.x4.shared.b16 {%0,%1,%2,%3}, [%4];"
                 : "=r"(r[0]), "=r"(r[1]), "=r"(r[2]), "=r"(r[3])
                 : "r"(addr));
}
__device__ __forceinline__ void mma_bf16(float* c, const uint32_t* a,
                                         const uint32_t* b) {
    asm volatile(
        "mma.sync.aligned.m16n8k16.row.col.f32.bf16.bf16.f32 "
        "{%0,%1,%2,%3}, {%4,%5,%6,%7}, {%8,%9}, {%0,%1,%2,%3};"
        : "+f"(c[0]), "+f"(c[1]), "+f"(c[2]), "+f"(c[3])
        : "r"(a[0]), "r"(a[1]), "r"(a[2]), "r"(a[3]), "r"(b[0]), "r"(b[1]));
}
__device__ __forceinline__ void split2(float x, float y, uint32_t& hi,
                                       uint32_t& lo) {
    __nv_bfloat16 hx = __float2bfloat16_rn(x);
    __nv_bfloat16 hy = __float2bfloat16_rn(y);
    hi = (uint32_t)__bfloat16_as_ushort(hx) |
         ((uint32_t)__bfloat16_as_ushort(hy) << 16);
    __nv_bfloat16 lx = __float2bfloat16_rn(x - __bfloat162float(hx));
    __nv_bfloat16 ly = __float2bfloat16_rn(y - __bfloat162float(hy));
    lo = (uint32_t)__bfloat16_as_ushort(lx) |
         ((uint32_t)__bfloat16_as_ushort(ly) << 16);
}

// Tile rows: 40 bf16 (80 bytes) -> conflict-free ldmatrix (stride 20 banks).
#define ROWB 80
#define TILE_BYTES (128 * ROWB)  // 10240; 4 tiles = 40960B static smem

// ===========================================================================
// GEMM: C[128,128] tile = A[M,K](fp32) @ B[N,K](bf16 hi/lo)^T + bias, blend.
// 512 threads = 16 warps in a 4(M) x 4(N) grid; warp tile 32x32. BK=32,
// single smem stage with register prefetch.  USE_WF selects weight globals.
// ===========================================================================
template <bool MASKED, bool USE_WF>
__global__ void __launch_bounds__(512, 1)
gemm_mma(const float* __restrict__ A, const float* __restrict__ bias,
         const float* __restrict__ HS, float* __restrict__ OUT,
         int K, int Ntot, int S) {
    __shared__ __align__(16) char sAh[TILE_BYTES];
    __shared__ __align__(16) char sAl[TILE_BYTES];
    __shared__ __align__(16) char sBh[TILE_BYTES];
    __shared__ __align__(16) char sBl[TILE_BYTES];
    __shared__ unsigned char smask[128];
    __shared__ int s_cnt;

    const __nv_bfloat16* __restrict__ Bh = USE_WF ? g_Wf_hi : g_Wt_hi;
    const __nv_bfloat16* __restrict__ Bl = USE_WF ? g_Wf_lo : g_Wt_lo;

    const int tid = threadIdx.x;
    const int wid = tid >> 5;
    const int lane = tid & 31;
    const int m0 = blockIdx.y * 128;
    const int n0 = blockIdx.x * 128;

    if (MASKED) {
        if (tid == 0) s_cnt = 0;
        __syncthreads();
        if (tid < 128) {
            unsigned char mm = g_mask[(m0 + tid) % S];
            smask[tid] = mm;
            if (mm) atomicAdd(&s_cnt, 1);
        }
        __syncthreads();
        if (s_cnt == 0) {  // all-public tile: straight copy of HS slab
            const size_t base = (size_t)m0 * Ntot + n0;
            for (int i = tid; i < 128 * 32; i += 512) {
                int r = i >> 5, c = (i & 31) << 2;
                *(float4*)&OUT[base + (size_t)r * Ntot + c] =
                    *(const float4*)&HS[base + (size_t)r * Ntot + c];
            }
            return;
        }
    }

    const uint32_t uAh = smem_u32(sAh);
    const uint32_t uAl = smem_u32(sAl);
    const uint32_t uBh = smem_u32(sBh);
    const uint32_t uBl = smem_u32(sBl);

    const int wm = (wid >> 2) * 32;  // warp M offset (4 rows of warps)
    const int wn = (wid & 3) * 32;   // warp N offset (4 cols of warps)

    const int lrow = tid >> 2;        // 0..127
    const int lcol = (tid & 3) * 8;   // 0,8,16,24

    float acc[2][4][4];
#pragma unroll
    for (int mt = 0; mt < 2; mt++)
#pragma unroll
        for (int nt = 0; nt < 4; nt++)
#pragma unroll
            for (int i = 0; i < 4; i++) acc[mt][nt][i] = 0.f;

    const int nk = K >> 5;
    float areg[8];
    uint4 bregh, bregl;

    auto load_regs = [&](int s) {
        const int k0 = s << 5;
        const float* ap = A + (size_t)(m0 + lrow) * K + k0 + lcol;
        *(float4*)&areg[0] = *(const float4*)(ap);
        *(float4*)&areg[4] = *(const float4*)(ap + 4);
        const size_t bo = (size_t)(n0 + lrow) * K + k0 + lcol;
        bregh = *(const uint4*)(Bh + bo);
        bregl = *(const uint4*)(Bl + bo);
    };
    auto store_stage = [&]() {
        uint32_t h[4], l[4];
#pragma unroll
        for (int i = 0; i < 4; i++)
            split2(areg[2 * i], areg[2 * i + 1], h[i], l[i]);
        const int off = lrow * ROWB + lcol * 2;
        *(uint4*)(sAh + off) = make_uint4(h[0], h[1], h[2], h[3]);
        *(uint4*)(sAl + off) = make_uint4(l[0], l[1], l[2], l[3]);
        *(uint4*)(sBh + off) = bregh;
        *(uint4*)(sBl + off) = bregl;
    };
    auto compute = [&]() {
        const int r8 = lane & 7;
        const int mat = lane >> 3;  // 0..3
#pragma unroll
        for (int ks = 0; ks < 2; ks++) {
            uint32_t ahf[2][4], alf[2][4];
#pragma unroll
            for (int mt = 0; mt < 2; mt++) {
                int arow = wm + mt * 16 + (mat & 1) * 8 + r8;
                int acol = ks * 16 + (mat >> 1) * 8;
                uint32_t off = (uint32_t)(arow * ROWB + acol * 2);
                ldsm_x4(uAh + off, ahf[mt]);
                ldsm_x4(uAl + off, alf[mt]);
            }
            uint32_t bhf[4][2], blf[4][2];
#pragma unroll
            for (int g = 0; g < 2; g++) {
                int brow = wn + g * 16 + (mat & 1) * 8 + r8;
                int bcol = ks * 16 + (mat >> 1) * 8;
                uint32_t off = (uint32_t)(brow * ROWB + bcol * 2);
                uint32_t t[4];
                ldsm_x4(uBh + off, t);
                bhf[2 * g][0] = t[0]; bhf[2 * g][1] = t[2];
                bhf[2 * g + 1][0] = t[1]; bhf[2 * g + 1][1] = t[3];
                ldsm_x4(uBl + off, t);
                blf[2 * g][0] = t[0]; blf[2 * g][1] = t[2];
                blf[2 * g + 1][0] = t[1]; blf[2 * g + 1][1] = t[3];
            }
#pragma unroll
            for (int mt = 0; mt < 2; mt++)
#pragma unroll
                for (int nt = 0; nt < 4; nt++) {
                    mma_bf16(acc[mt][nt], ahf[mt], bhf[nt]);
                    mma_bf16(acc[mt][nt], ahf[mt], blf[nt]);
                    mma_bf16(acc[mt][nt], alf[mt], bhf[nt]);
                }
        }
    };

    // Main loop: single smem stage, register prefetch of next chunk.
    load_regs(0);
    for (int s = 0; s < nk; s++) {
        store_stage();
        __syncthreads();
        if (s + 1 < nk) load_regs(s + 1);  // globals in flight during compute
        compute();
        __syncthreads();
    }

    // Epilogue
    const int qr = lane >> 2;
    const int qc = (lane & 3) * 2;
#pragma unroll
    for (int mt = 0; mt < 2; mt++) {
        const int lr0 = wm + mt * 16 + qr;
        const int lr1 = lr0 + 8;
        const size_t rb0 = (size_t)(m0 + lr0) * Ntot;
        const size_t rb1 = (size_t)(m0 + lr1) * Ntot;
        const bool p0 = !MASKED || (smask[lr0] != 0);
        const bool p1 = !MASKED || (smask[lr1] != 0);
#pragma unroll
        for (int nt = 0; nt < 4; nt++) {
            const int col = n0 + wn + nt * 8 + qc;
            float2 b2 = *(const float2*)&bias[col];
            float2 v0, v1;
            if (p0) {
                v0.x = acc[mt][nt][0] + b2.x;
                v0.y = acc[mt][nt][1] + b2.y;
            } else {
                v0 = *(const float2*)&HS[rb0 + col];
            }
            if (p1) {
                v1.x = acc[mt][nt][2] + b2.x;
                v1.y = acc[mt][nt][3] + b2.y;
            } else {
                v1 = *(const float2*)&HS[rb1 + col];
            }
            *(float2*)&OUT[rb0 + col] = v0;
            *(float2*)&OUT[rb1 + col] = v1;
        }
    }
}

// ===========================================================================
// Mask scan, broadcast, weight split kernels.
// ===========================================================================
__global__ void scan_kernel(const int* __restrict__ tok,
                            const int* __restrict__ ttid_p,
                            float* __restrict__ usage_out, int B, int S) {
    __shared__ int stok[8192];
    __shared__ int sc[256];
    const int ttid = *ttid_p;
    const int tid = threadIdx.x;
    const bool fits = (S <= 8192);
    if (fits)
        for (int i = tid; i < S; i += 256) stok[i] = tok[i];
    __syncthreads();
    const int* src = fits ? stok : tok;

    const int chunk = (S + 255) / 256;
    const int start = tid * chunk;
    const int end = min(start + chunk, S);
    int cnt = 0;
    for (int i = start; i < end; i++) cnt += (src[i] == ttid);
    sc[tid] = cnt;
    __syncthreads();
    for (int off = 1; off < 256; off <<= 1) {
        int v = (tid >= off) ? sc[tid - off] : 0;
        __syncthreads();
        sc[tid] += v;
        __syncthreads();
    }
    int run = sc[tid] - cnt;
    int ones = 0;
    for (int i = start; i < end; i++) {
        run += (src[i] == ttid);
        unsigned char m = (unsigned char)(run & 1);
        g_mask[i] = m;
        ones += m;
    }
    __syncthreads();
    sc[tid] = ones;
    __syncthreads();
    for (int off = 128; off > 0; off >>= 1) {
        if (tid < off) sc[tid] += sc[tid + off];
        __syncthreads();
    }
    if (tid < B) usage_out[tid] = (float)sc[0] / (float)S;
}

__global__ void bcast_kernel(float* __restrict__ out_mask, int BS, int S) {
    int i = blockIdx.x * blockDim.x + threadIdx.x;
    if (i < BS) out_mask[i] = (float)g_mask[i % S];
}

__global__ void conv_w_kernel(const float* __restrict__ W_to,
                              const float* __restrict__ W_from, int H, int P) {
    int idx = blockIdx.x * blockDim.x + threadIdx.x;
    if (idx >= H * P) return;
    {  // W_to [H][P] -> Wt [P][H]
        float v = W_to[idx];
        int k = idx / P, n = idx - k * P;
        __nv_bfloat16 h = __float2bfloat16_rn(v);
        g_Wt_hi[n * H + k] = h;
        g_Wt_lo[n * H + k] = __float2bfloat16_rn(v - __bfloat162float(h));
    }
    {  // W_from [P][H] -> Wf [H][P]
        float v = W_from[idx];
        int p = idx / H, hh = idx - p * H;
        __nv_bfloat16 h = __float2bfloat16_rn(v);
        g_Wf_hi[hh * P + p] = h;
        g_Wf_lo[hh * P + p] = __float2bfloat16_rn(v - __bfloat162float(h));
    }
}

// ===========================================================================
extern "C" void kernel_launch(void* const* d_in, const int* in_sizes, int n_in,
                              void* d_out, int out_size) {
    const float* hidden = (const float*)d_in[0];
    const float* W_to   = (const float*)d_in[1];
    const float* b_to   = (const float*)d_in[2];
    const float* W_from = (const float*)d_in[3];
    const float* b_from = (const float*)d_in[4];
    const int*   token  = (const int*)d_in[5];
    const int*   ttid   = (const int*)d_in[6];

    const int P  = in_sizes[2];
    const int H  = in_sizes[4];
    const int BS = in_sizes[5];
    const int B  = out_size - BS * (P + H + 1);
    const int S  = BS / B;

    float* out = (float*)d_out;
    float* out_pr    = out;
    float* out_o     = out + (size_t)BS * P;
    float* out_mask  = out_o + (size_t)BS * H;
    float* out_usage = out_mask + BS;

    scan_kernel<<<1, 256>>>(token, ttid, out_usage, B, S);
    bcast_kernel<<<(BS + 255) / 256, 256>>>(out_mask, BS, S);
    conv_w_kernel<<<(H * P + 255) / 256, 256>>>(W_to, W_from, H, P);

    // GEMM1: PR = HS @ W_to + b_to   (M=BS, N=P, K=H)
    gemm_mma<false, false><<<dim3(P / 128, BS / 128), 512>>>(
        hidden, b_to, nullptr, out_pr, H, P, S);

    // GEMM2: OUT = blend(PR @ W_from + b_from, HS)  (M=BS, N=H, K=P)
    gemm_mma<true, true><<<dim3(H / 128, BS / 128), 512>>>(
        out_pr, b_from, hidden, out_o, P, H, S);
}